// round 15
// baseline (speedup 1.0000x reference)
#include <cuda_runtime.h>
#include <math.h>

#define B_ 64
#define T_ 512
#define H_ 256
#define G_ 1024
#define BH_ (B_*H_)
#define BT_ (B_*T_)
#define MPAR_ 37
#define NRNK_ 8
#define NCTA_ (MPAR_*NRNK_)   // 296 = 2 per SM

// ---------------- static device scratch (no allocations) ----------------
__device__ float g_x [(size_t)T_*B_*256];   // x,  row m = t*64+b
__device__ float g_gx[(size_t)T_*B_*G_];    // gx, row m = t*64+b
__device__ float g_h [(size_t)(T_+1)*BH_];  // h history [(T+1), B, H]
__device__ float g_c [(size_t)(T_+1)*BH_];  // c history
// levelization
__device__ int      g_nodes[BT_];           // packed (b<<20)|(t<<10)|fidx, level-major
__device__ int      g_cntB [B_*512];        // [b][lvl]
__device__ int      g_off2 [512*B_];        // [lvl][b] start slot
__device__ int      g_lvlOff[513];
__device__ int      g_D[1];
__device__ unsigned g_bar;                  // scan grid barrier (reset by lvlall)
__device__ unsigned g_cnt2;                 // lvlall sense barrier (self-restoring)
__device__ unsigned g_sns;

typedef unsigned long long u64;
typedef unsigned int u32;

// ---------------- f32x2 helpers ----------------
__device__ __forceinline__ u64 fma2(u64 a, u64 b, u64 c){
    u64 d; asm("fma.rn.f32x2 %0, %1, %2, %3;" : "=l"(d) : "l"(a), "l"(b), "l"(c)); return d;
}
__device__ __forceinline__ u64 pack2(float x, float y){
    u64 d; asm("mov.b64 %0, {%1, %2};" : "=l"(d)
               : "r"(__float_as_uint(x)), "r"(__float_as_uint(y))); return d;
}
__device__ __forceinline__ float2 unp2(u64 v){
    u32 lo, hi; asm("mov.b64 {%0, %1}, %2;" : "=r"(lo), "=r"(hi) : "l"(v));
    return make_float2(__uint_as_float(lo), __uint_as_float(hi));
}
__device__ __forceinline__ float sigm(float x){ return 1.0f/(1.0f + __expf(-x)); }
__device__ __forceinline__ float tanh_f(float x){   // accurate for tiny x, cheap
    float ax = fabsf(x);
    if(ax < 0.25f){
        float x2 = x*x;
        return x*(1.0f + x2*(-0.33333333f + x2*(0.13333333f - x2*0.053968254f)));
    }
    return tanhf(x);
}

// ---------------- cp.async helpers ----------------
__device__ __forceinline__ void cpasync16(u32 dst, const void* src){
    asm volatile("cp.async.ca.shared.global [%0], [%1], 16;" :: "r"(dst), "l"(src));
}
#define CP_COMMIT() asm volatile("cp.async.commit_group;" ::: "memory")
#define CP_WAIT0()  asm volatile("cp.async.wait_group 0;"  ::: "memory")

// ---------------- embedding gather + mean + concat ----------------
__global__ __launch_bounds__(128)
void embed_kernel(const int* __restrict__ node, const int* __restrict__ rel,
                  const float* __restrict__ emb)
{
    int pos  = blockIdx.x*4 + (threadIdx.x >> 5);   // pos = b*T + t
    int lane = threadIdx.x & 31;
    int b = pos >> 9, t = pos & 511;
    const float4* E = (const float4*)emb;
    int n0 = __ldg(&node[pos*2+0]);
    int n1 = __ldg(&node[pos*2+1]);
    int r0 = __ldg(&rel[pos*3+0]);
    int r1 = __ldg(&rel[pos*3+1]);
    int r2 = __ldg(&rel[pos*3+2]);
    float4 e0 = __ldg(&E[(size_t)n0*32 + lane]);
    float4 e1 = __ldg(&E[(size_t)n1*32 + lane]);
    float4 f0 = __ldg(&E[(size_t)r0*32 + lane]);
    float4 f1 = __ldg(&E[(size_t)r1*32 + lane]);
    float4 f2 = __ldg(&E[(size_t)r2*32 + lane]);
    float4 nv = make_float4(0.5f*(e0.x+e1.x), 0.5f*(e0.y+e1.y),
                            0.5f*(e0.z+e1.z), 0.5f*(e0.w+e1.w));
    const float th = (1.0f/3.0f);
    float4 rv = make_float4(th*(f0.x+f1.x+f2.x), th*(f0.y+f1.y+f2.y),
                            th*(f0.z+f1.z+f2.z), th*(f0.w+f1.w+f2.w));
    float4* xr = (float4*)(g_x + ((size_t)t*B_ + b)*256);
    xr[lane]      = nv;
    xr[32 + lane] = rv;
}

// ---------------- SGEMM (NT): C[M,N] = A[M,K] * Bw[N,K]^T (+ bias[N]) ----------------
__global__ __launch_bounds__(256, 2)
void sgemm_nt(const float* __restrict__ A, const float* __restrict__ Bw,
              const float* __restrict__ bias, float* __restrict__ C,
              int M, int N, int K)
{
    __shared__ __align__(16) float As[16][128];
    __shared__ __align__(16) float Bs[16][128];
    int tid = threadIdx.x;
    int m0 = blockIdx.y * 128;
    int n0 = blockIdx.x * 128;
    int tx = tid & 15, ty = tid >> 4;

    int r0_ = tid & 127,        kq0 = (tid >> 7);
    int r1_ = r0_,              kq1 = kq0 + 2;

    u64 acc[8][4];
#pragma unroll
    for(int i=0;i<8;i++)
#pragma unroll
        for(int j=0;j<4;j++) acc[i][j] = 0ull;

    float4 av0, av1, bv0, bv1;
    av0 = __ldg((const float4*)(A  + (size_t)(m0+r0_)*K + kq0*4));
    av1 = __ldg((const float4*)(A  + (size_t)(m0+r1_)*K + kq1*4));
    bv0 = __ldg((const float4*)(Bw + (size_t)(n0+r0_)*K + kq0*4));
    bv1 = __ldg((const float4*)(Bw + (size_t)(n0+r1_)*K + kq1*4));
    As[kq0*4+0][r0_]=av0.x; As[kq0*4+1][r0_]=av0.y; As[kq0*4+2][r0_]=av0.z; As[kq0*4+3][r0_]=av0.w;
    As[kq1*4+0][r1_]=av1.x; As[kq1*4+1][r1_]=av1.y; As[kq1*4+2][r1_]=av1.z; As[kq1*4+3][r1_]=av1.w;
    Bs[kq0*4+0][r0_]=bv0.x; Bs[kq0*4+1][r0_]=bv0.y; Bs[kq0*4+2][r0_]=bv0.z; Bs[kq0*4+3][r0_]=bv0.w;
    Bs[kq1*4+0][r1_]=bv1.x; Bs[kq1*4+1][r1_]=bv1.y; Bs[kq1*4+2][r1_]=bv1.z; Bs[kq1*4+3][r1_]=bv1.w;
    __syncthreads();

    for(int kt=0; kt<K; kt+=16){
        bool more = (kt+16 < K);
        if(more){
            av0 = __ldg((const float4*)(A  + (size_t)(m0+r0_)*K + kt+16 + kq0*4));
            av1 = __ldg((const float4*)(A  + (size_t)(m0+r1_)*K + kt+16 + kq1*4));
            bv0 = __ldg((const float4*)(Bw + (size_t)(n0+r0_)*K + kt+16 + kq0*4));
            bv1 = __ldg((const float4*)(Bw + (size_t)(n0+r1_)*K + kt+16 + kq1*4));
        }
#pragma unroll
        for(int k=0;k<16;k++){
            float4 a0 = *(const float4*)&As[k][ty*8];
            float4 a1 = *(const float4*)&As[k][ty*8+4];
            u64 b0 = *(const u64*)&Bs[k][tx*2];
            u64 b1 = *(const u64*)&Bs[k][tx*2 + 32];
            u64 b2 = *(const u64*)&Bs[k][tx*2 + 64];
            u64 b3 = *(const u64*)&Bs[k][tx*2 + 96];
            float af[8] = {a0.x,a0.y,a0.z,a0.w,a1.x,a1.y,a1.z,a1.w};
#pragma unroll
            for(int i=0;i<8;i++){
                u64 aa = pack2(af[i], af[i]);
                acc[i][0] = fma2(aa, b0, acc[i][0]);
                acc[i][1] = fma2(aa, b1, acc[i][1]);
                acc[i][2] = fma2(aa, b2, acc[i][2]);
                acc[i][3] = fma2(aa, b3, acc[i][3]);
            }
        }
        if(more){
            __syncthreads();
            As[kq0*4+0][r0_]=av0.x; As[kq0*4+1][r0_]=av0.y; As[kq0*4+2][r0_]=av0.z; As[kq0*4+3][r0_]=av0.w;
            As[kq1*4+0][r1_]=av1.x; As[kq1*4+1][r1_]=av1.y; As[kq1*4+2][r1_]=av1.z; As[kq1*4+3][r1_]=av1.w;
            Bs[kq0*4+0][r0_]=bv0.x; Bs[kq0*4+1][r0_]=bv0.y; Bs[kq0*4+2][r0_]=bv0.z; Bs[kq0*4+3][r0_]=bv0.w;
            Bs[kq1*4+0][r1_]=bv1.x; Bs[kq1*4+1][r1_]=bv1.y; Bs[kq1*4+2][r1_]=bv1.z; Bs[kq1*4+3][r1_]=bv1.w;
            __syncthreads();
        }
    }
#pragma unroll
    for(int i=0;i<8;i++){
        float* cp = C + (size_t)(m0 + ty*8 + i)*N + n0;
#pragma unroll
        for(int j=0;j<4;j++){
            float2 v = unp2(acc[i][j]);
            int col = 32*j + 2*tx;
            if(bias){
                v.x += __ldg(&bias[n0 + col    ]);
                v.y += __ldg(&bias[n0 + col + 1]);
            }
            *(float2*)(cp + col) = v;
        }
    }
}

// ---------------- merged levelizer (64 CTAs x 512, 2 internal grid barriers) ----------
__device__ __forceinline__ void gbar64(unsigned &ls){
    __syncthreads();
    if(threadIdx.x == 0){
        unsigned s = ls ^ 1u;
        __threadfence();
        unsigned a = atomicAdd(&g_cnt2, 1u);
        if(a == 63u){
            atomicExch(&g_cnt2, 0u);
            atomicExch(&g_sns, s);
        } else {
            while(atomicAdd(&g_sns, 0u) != s) __nanosleep(32);
        }
        __threadfence();
        ls = s;
    }
    __syncthreads();
}

__global__ __launch_bounds__(512)
void lvlall_kernel(const int* __restrict__ father)
{
    __shared__ int anc[2][512], dep[2][512], slvl[512], cnt[512];
    int t = threadIdx.x, b = blockIdx.x;
    unsigned ls = 0;

    int f  = __ldg(&father[b*T_ + t]);
    int fx = min(f, t-1) + 1;                  // in [0, t]
    anc[0][t] = fx - 1;
    dep[0][t] = (fx > 0) ? 1 : 0;
    cnt[t] = 0;
    __syncthreads();
#pragma unroll
    for(int r=0; r<9; r++){
        int cur = r & 1, nxt = cur ^ 1;
        int a = anc[cur][t], d = dep[cur][t];
        if(a >= 0){ d += dep[cur][a]; a = anc[cur][a]; }
        anc[nxt][t] = a; dep[nxt][t] = d;
        __syncthreads();
    }
    int L = dep[1][t];
    slvl[t] = L;
    atomicAdd(&cnt[L], 1);
    __syncthreads();
    int rk = 0;
    for(int tp=0; tp<t; tp++) rk += (slvl[tp] == L);
    g_cntB[b*512 + t] = cnt[t];

    gbar64(ls);

    if(b == 0){
        __shared__ int off[513];
        int s = 0;
        for(int bb=0; bb<B_; bb++) s += g_cntB[bb*512 + t];
        slvl[t] = s;
        __syncthreads();
        if(t == 0){
            int run = 0, D = 1;
            for(int i=0;i<512;i++){
                off[i] = run; run += slvl[i];
                if(slvl[i] > 0) D = i+1;
            }
            off[512] = run;
            g_D[0] = D;
            g_bar  = 0;
        }
        __syncthreads();
        g_lvlOff[t] = off[t];
        if(t == 0) g_lvlOff[512] = off[512];
        int run2 = off[t];
        for(int bb=0; bb<B_; bb++){
            g_off2[t*B_ + bb] = run2;
            run2 += g_cntB[bb*512 + t];
        }
    }

    gbar64(ls);

    int slot = g_off2[L*B_ + b] + rk;
    g_nodes[slot] = (b << 20) | (t << 10) | fx;
    int z = b*512 + t;
    if(z < BH_){ g_h[z] = 0.0f; g_c[z] = 0.0f; }
}

// ---------------- persistent levelized scan (v3b: outer-product, aligned) ----------
// 296 CTAs = 37 M-slots x 8 ranks (2/SM). CTA(rank): units [32r,32r+32), all 4
// gates -> 128 gate rows. C[32 nodes][128 rows] = h @ W^T, sgemm-style:
// h node-major via cp.async; W streamed k-major, double-buffered 32-k chunks.
// Thread (rg=tid&15, ng=tid>>4): nodes {2ng,2ng+1}, row-pairs {32j+2rg, +1} j=0..3
// -> W u64 reads at float offset k*WP_ + 32j + 2rg: even (aligned) + banks 2rg
// distinct across lanes (conflict-free).
#define HP_ 260          // hs node stride (floats), 16B-aligned
#define WP_ 130          // Ws k stride (floats), EVEN -> u64-aligned
struct ScanSm {
    float hs[32*HP_];        // gathered h, node-major
    float Ws[2][32*WP_];     // W chunk, k-major [k][row]
    float qb[32*128];        // gates [node][row], row = gate*32 + unit
};

__global__ __launch_bounds__(256, 2)
void scan_kernel(const float* __restrict__ W_hh, const float* __restrict__ b_hh,
                 const float* __restrict__ mask, float* __restrict__ out)
{
    extern __shared__ __align__(16) char smraw[];
    ScanSm* S = (ScanSm*)smraw;
    u32 hs_s = (u32)__cvta_generic_to_shared(&S->hs[0]);

    int tid  = threadIdx.x;
    int rank = blockIdx.x & 7;
    int msl  = blockIdx.x >> 3;                // 0..36
    int u0   = rank * 32;
    int rg   = tid & 15;                       // row-pair selector
    int ng   = tid >> 4;                       // node-group: nodes 2ng, 2ng+1
    int n0   = 2*ng, n1 = 2*ng + 1;

    // W staging ids: thread covers row wlr, k wkq..wkq+15 of each 32-k chunk
    int wlr = tid & 127;
    int wkq = (tid >> 7) * 16;
    int wgrow = (wlr >> 5)*256 + u0 + (wlr & 31);
    const float4* wsrc = (const float4*)(W_hh + (size_t)wgrow*256);

    // cell ids
    int cu  = tid & 31;
    int gu  = u0 + cu;
    int cn0 = tid >> 5;                        // 0..7
    float bh4[4];
#pragma unroll
    for(int g=0; g<4; g++) bh4[g] = __ldg(&b_hh[g*256 + gu]);

    int D = g_D[0];
    unsigned phase = 0;

    for(int l=0; l<D; l++){
        int o0 = g_lvlOff[l], o1 = g_lvlOff[l+1];
        int ntile = (o1 - o0 + 31) >> 5;

        for(int mt = msl; mt < ntile; mt += MPAR_){
            int base = o0 + mt*32;
            int nn   = min(32, o1 - base);

            // (1) gather h tile via cp.async (node-major)
#pragma unroll
            for(int j=0;j<8;j++){
                int lin = j*256 + tid;
                int n = lin >> 6, p = lin & 63;
                if(n < nn){
                    int v  = __ldg(&g_nodes[base + n]);
                    int fx = v & 1023, bb = v >> 20;
                    const float4* src = (const float4*)(g_h + (size_t)fx*BH_ + bb*256) + p;
                    cpasync16(hs_s + (u32)((n*HP_ + p*4)*4), src);
                }
            }
            CP_COMMIT();

            // (2) prefetch cell operands (gx, c_prev, mask) into regs
            float gxp[4][4], cpp[4], mvp[4];
#pragma unroll
            for(int e=0;e<4;e++){
                int n = e*8 + cn0;
                if(n < nn){
                    int v  = __ldg(&g_nodes[base + n]);
                    int fx = v & 1023; int t = (v >> 10) & 1023; int bb = v >> 20;
                    size_t gxr = ((size_t)t*B_ + bb)*G_;
#pragma unroll
                    for(int g=0; g<4; g++) gxp[e][g] = __ldg(&g_gx[gxr + g*256 + gu]);
                    cpp[e] = __ldg(&g_c[(size_t)fx*BH_ + bb*256 + gu]);
                    mvp[e] = __ldg(&mask[bb*T_ + t]);
                }
            }

            // (3) load W chunk 0 into regs
            float4 wv[4];
#pragma unroll
            for(int i=0;i<4;i++) wv[i] = __ldg(wsrc + (wkq >> 2) + i);

            CP_WAIT0();
            // STS chunk 0
#pragma unroll
            for(int i=0;i<4;i++){
                float* wd = &S->Ws[0][(wkq + i*4)*WP_ + wlr];
                wd[0*WP_] = wv[i].x; wd[1*WP_] = wv[i].y;
                wd[2*WP_] = wv[i].z; wd[3*WP_] = wv[i].w;
            }
            __syncthreads();     // hs + Ws[0] visible

            // (4) k-chunk loop with double-buffered Ws
            u64 acc0[4] = {0,0,0,0}, acc1[4] = {0,0,0,0};
            int buf = 0;
#pragma unroll
            for(int kc=0; kc<8; kc++){
                if(kc < 7){
#pragma unroll
                    for(int i=0;i<4;i++)
                        wv[i] = __ldg(wsrc + (kc+1)*8 + (wkq >> 2) + i);
                }
                const float* hrow0 = S->hs + n0*HP_ + kc*32;
                const float* hrow1 = S->hs + n1*HP_ + kc*32;
                const float* wsb   = &S->Ws[buf][0];
#pragma unroll
                for(int k=0;k<32;k++){
                    float h0 = hrow0[k], h1 = hrow1[k];
                    u64 a0 = pack2(h0,h0), a1 = pack2(h1,h1);
                    const u64* wr = (const u64*)(wsb + k*WP_) + rg;   // +16*j per row-pair
                    u64 w0 = wr[0], w1 = wr[16], w2 = wr[32], w3 = wr[48];
                    acc0[0] = fma2(a0, w0, acc0[0]);
                    acc1[0] = fma2(a1, w0, acc1[0]);
                    acc0[1] = fma2(a0, w1, acc0[1]);
                    acc1[1] = fma2(a1, w1, acc1[1]);
                    acc0[2] = fma2(a0, w2, acc0[2]);
                    acc1[2] = fma2(a1, w2, acc1[2]);
                    acc0[3] = fma2(a0, w3, acc0[3]);
                    acc1[3] = fma2(a1, w3, acc1[3]);
                }
                if(kc < 7){
#pragma unroll
                    for(int i=0;i<4;i++){
                        float* wd = &S->Ws[buf^1][(wkq + i*4)*WP_ + wlr];
                        wd[0*WP_] = wv[i].x; wd[1*WP_] = wv[i].y;
                        wd[2*WP_] = wv[i].z; wd[3*WP_] = wv[i].w;
                    }
                    __syncthreads();
                    buf ^= 1;
                }
            }

            // (5) qb stores: acc[j] -> rows {32j+2rg, 32j+2rg+1}
            if(n0 < nn){
#pragma unroll
                for(int j=0;j<4;j++)
                    *(float2*)&S->qb[n0*128 + 32*j + 2*rg] = unp2(acc0[j]);
            }
            if(n1 < nn){
#pragma unroll
                for(int j=0;j<4;j++)
                    *(float2*)&S->qb[n1*128 + 32*j + 2*rg] = unp2(acc1[j]);
            }
            __syncthreads();

            // (6) fused LSTM cell: 32 nodes x 32 units -> 4 per thread
#pragma unroll
            for(int e=0;e<4;e++){
                int n = e*8 + cn0;
                if(n < nn){
                    int v  = __ldg(&g_nodes[base + n]);
                    int t = (v >> 10) & 1023; int bb = v >> 20;
                    float gi = S->qb[n*128 +      cu] + gxp[e][0] + bh4[0];
                    float gf = S->qb[n*128 + 32 + cu] + gxp[e][1] + bh4[1];
                    float gg = S->qb[n*128 + 64 + cu] + gxp[e][2] + bh4[2];
                    float go = S->qb[n*128 + 96 + cu] + gxp[e][3] + bh4[3];
                    float cv = sigm(gf)*cpp[e] + sigm(gi)*tanh_f(gg);
                    float hv = sigm(go)*tanh_f(cv);
                    size_t o = (size_t)(t+1)*BH_ + bb*256 + gu;
                    g_h[o] = hv;
                    g_c[o] = cv;
                    out[(size_t)bb*(T_*H_) + (size_t)t*H_ + gu] = hv*mvp[e];
                }
            }
        }

        // grid barrier between levels (monotonic; g_bar reset by lvlall each call)
        phase++;
        __threadfence();
        __syncthreads();
        if(tid == 0){
            atomicAdd(&g_bar, 1u);
            unsigned target = phase * NCTA_;
            while(*((volatile unsigned*)&g_bar) < target) __nanosleep(64);
            __threadfence();
        }
        __syncthreads();
    }
}

// ---------------- masked max epilogue ----------------
__global__ __launch_bounds__(256)
void maxes_kernel(const float* __restrict__ mask, float* __restrict__ out)
{
    int idx = blockIdx.x*256 + threadIdx.x;     // 0..BH-1
    int b = idx >> 8, u = idx & 255;
    float hm = -1e30f, cm = -1e30f;
    for(int t=0; t<T_; t++){
        float h  = out[(size_t)b*(T_*H_) + (size_t)t*H_ + u];
        float mv = __ldg(&mask[b*T_ + t]);
        float c  = g_c[(size_t)(t+1)*BH_ + b*256 + u] * mv;
        hm = fmaxf(hm, h);
        cm = fmaxf(cm, c);
    }
    size_t base = (size_t)2*B_*T_*H_;
    out[base +        idx] = hm;
    out[base + BH_ +  idx] = cm;
}

extern "C" void kernel_launch(void* const* d_in, const int* in_sizes, int n_in,
                              void* d_out, int out_size)
{
    const int*   node   = (const int*)  d_in[0];
    const int*   rel    = (const int*)  d_in[1];
    const int*   father = (const int*)  d_in[2];
    const float* mask   = (const float*)d_in[3];
    const float* emb    = (const float*)d_in[4];
    const float* W_ih   = (const float*)d_in[5];
    const float* W_hh   = (const float*)d_in[6];
    const float* b_ih   = (const float*)d_in[7];
    const float* b_hh   = (const float*)d_in[8];
    const float* W_h    = (const float*)d_in[9];
    float* out = (float*)d_out;

    float *px, *pgx;
    cudaGetSymbolAddress((void**)&px,  g_x);
    cudaGetSymbolAddress((void**)&pgx, g_gx);

    embed_kernel<<<(B_*T_)/4, 128>>>(node, rel, emb);           // launch 1

    dim3 g1(G_/128, (B_*T_)/128);
    sgemm_nt<<<g1, 256>>>(px, W_ih, b_ih, pgx, B_*T_, G_, 256); // launch 2

    lvlall_kernel<<<B_, 512>>>(father);                          // launch 3

    cudaFuncSetAttribute(scan_kernel, cudaFuncAttributeMaxDynamicSharedMemorySize,
                         (int)sizeof(ScanSm));
    scan_kernel<<<NCTA_, 256, sizeof(ScanSm)>>>(W_hh, b_hh, mask, out);  // launch 4 (profiled)

    maxes_kernel<<<BH_/256, 256>>>(mask, out);                   // launch 5

    dim3 g2(H_/128, (B_*T_)/128);
    sgemm_nt<<<g2, 256>>>(out, W_h, (const float*)nullptr,
                          out + (size_t)B_*T_*H_, B_*T_, H_, 256);  // launch 6
}

// round 16
// speedup vs baseline: 1.4533x; 1.4533x over previous
#include <cuda_runtime.h>
#include <math.h>

#define B_ 64
#define T_ 512
#define H_ 256
#define G_ 1024
#define BH_ (B_*H_)
#define BT_ (B_*T_)
#define MPAR_ 18
#define NRNK_ 16
#define NCTA_ (MPAR_*NRNK_)

// ---------------- static device scratch (no allocations) ----------------
__device__ float g_x [(size_t)T_*B_*256];   // x,  row m = t*64+b
__device__ float g_gx[(size_t)T_*B_*G_];    // gx, row m = t*64+b
__device__ float g_h [(size_t)(T_+1)*BH_];  // h history [(T+1), B, H]
__device__ float g_c [(size_t)(T_+1)*BH_];  // c history
// levelization
__device__ int      g_nodes[BT_];           // packed (b<<20)|(t<<10)|fidx, level-major
__device__ int      g_cntB [B_*512];        // [b][lvl]
__device__ int      g_off2 [512*B_];        // [lvl][b] start slot
__device__ int      g_lvlOff[513];
__device__ int      g_D[1];
__device__ unsigned g_bar;                  // scan grid barrier (reset by lvlall)
__device__ unsigned g_cnt2;                 // lvlall sense barrier (self-restoring)
__device__ unsigned g_sns;

typedef unsigned long long u64;
typedef unsigned int u32;

// ---------------- f32x2 helpers ----------------
__device__ __forceinline__ u64 fma2(u64 a, u64 b, u64 c){
    u64 d; asm("fma.rn.f32x2 %0, %1, %2, %3;" : "=l"(d) : "l"(a), "l"(b), "l"(c)); return d;
}
__device__ __forceinline__ u64 pack2(float x, float y){
    u64 d; asm("mov.b64 %0, {%1, %2};" : "=l"(d)
               : "r"(__float_as_uint(x)), "r"(__float_as_uint(y))); return d;
}
__device__ __forceinline__ float2 unp2(u64 v){
    u32 lo, hi; asm("mov.b64 {%0, %1}, %2;" : "=r"(lo), "=r"(hi) : "l"(v));
    return make_float2(__uint_as_float(lo), __uint_as_float(hi));
}
__device__ __forceinline__ float sigm(float x){ return 1.0f/(1.0f + __expf(-x)); }
__device__ __forceinline__ float tanh_f(float x){   // accurate for tiny x, cheap
    float ax = fabsf(x);
    if(ax < 0.25f){
        float x2 = x*x;
        return x*(1.0f + x2*(-0.33333333f + x2*(0.13333333f - x2*0.053968254f)));
    }
    return tanhf(x);
}

// ---------------- cp.async helpers ----------------
__device__ __forceinline__ void cpasync16(u32 dst, const void* src){
    asm volatile("cp.async.ca.shared.global [%0], [%1], 16;" :: "r"(dst), "l"(src));
}
#define CP_COMMIT() asm volatile("cp.async.commit_group;" ::: "memory")
#define CP_WAIT0()  asm volatile("cp.async.wait_group 0;"  ::: "memory")

// ---------------- embedding gather + mean + concat ----------------
__global__ __launch_bounds__(128)
void embed_kernel(const int* __restrict__ node, const int* __restrict__ rel,
                  const float* __restrict__ emb)
{
    int pos  = blockIdx.x*4 + (threadIdx.x >> 5);   // pos = b*T + t
    int lane = threadIdx.x & 31;
    int b = pos >> 9, t = pos & 511;
    const float4* E = (const float4*)emb;
    int n0 = __ldg(&node[pos*2+0]);
    int n1 = __ldg(&node[pos*2+1]);
    int r0 = __ldg(&rel[pos*3+0]);
    int r1 = __ldg(&rel[pos*3+1]);
    int r2 = __ldg(&rel[pos*3+2]);
    float4 e0 = __ldg(&E[(size_t)n0*32 + lane]);
    float4 e1 = __ldg(&E[(size_t)n1*32 + lane]);
    float4 f0 = __ldg(&E[(size_t)r0*32 + lane]);
    float4 f1 = __ldg(&E[(size_t)r1*32 + lane]);
    float4 f2 = __ldg(&E[(size_t)r2*32 + lane]);
    float4 nv = make_float4(0.5f*(e0.x+e1.x), 0.5f*(e0.y+e1.y),
                            0.5f*(e0.z+e1.z), 0.5f*(e0.w+e1.w));
    const float th = (1.0f/3.0f);
    float4 rv = make_float4(th*(f0.x+f1.x+f2.x), th*(f0.y+f1.y+f2.y),
                            th*(f0.z+f1.z+f2.z), th*(f0.w+f1.w+f2.w));
    float4* xr = (float4*)(g_x + ((size_t)t*B_ + b)*256);
    xr[lane]      = nv;
    xr[32 + lane] = rv;
}

// ---------------- SGEMM (NT): C[M,N] = A[M,K] * Bw[N,K]^T (+ bias[N]) ----------------
__global__ __launch_bounds__(256, 2)
void sgemm_nt(const float* __restrict__ A, const float* __restrict__ Bw,
              const float* __restrict__ bias, float* __restrict__ C,
              int M, int N, int K)
{
    __shared__ __align__(16) float As[16][128];
    __shared__ __align__(16) float Bs[16][128];
    int tid = threadIdx.x;
    int m0 = blockIdx.y * 128;
    int n0 = blockIdx.x * 128;
    int tx = tid & 15, ty = tid >> 4;

    int r0_ = tid & 127,        kq0 = (tid >> 7);
    int r1_ = r0_,              kq1 = kq0 + 2;

    u64 acc[8][4];
#pragma unroll
    for(int i=0;i<8;i++)
#pragma unroll
        for(int j=0;j<4;j++) acc[i][j] = 0ull;

    float4 av0, av1, bv0, bv1;
    av0 = __ldg((const float4*)(A  + (size_t)(m0+r0_)*K + kq0*4));
    av1 = __ldg((const float4*)(A  + (size_t)(m0+r1_)*K + kq1*4));
    bv0 = __ldg((const float4*)(Bw + (size_t)(n0+r0_)*K + kq0*4));
    bv1 = __ldg((const float4*)(Bw + (size_t)(n0+r1_)*K + kq1*4));
    As[kq0*4+0][r0_]=av0.x; As[kq0*4+1][r0_]=av0.y; As[kq0*4+2][r0_]=av0.z; As[kq0*4+3][r0_]=av0.w;
    As[kq1*4+0][r1_]=av1.x; As[kq1*4+1][r1_]=av1.y; As[kq1*4+2][r1_]=av1.z; As[kq1*4+3][r1_]=av1.w;
    Bs[kq0*4+0][r0_]=bv0.x; Bs[kq0*4+1][r0_]=bv0.y; Bs[kq0*4+2][r0_]=bv0.z; Bs[kq0*4+3][r0_]=bv0.w;
    Bs[kq1*4+0][r1_]=bv1.x; Bs[kq1*4+1][r1_]=bv1.y; Bs[kq1*4+2][r1_]=bv1.z; Bs[kq1*4+3][r1_]=bv1.w;
    __syncthreads();

    for(int kt=0; kt<K; kt+=16){
        bool more = (kt+16 < K);
        if(more){
            av0 = __ldg((const float4*)(A  + (size_t)(m0+r0_)*K + kt+16 + kq0*4));
            av1 = __ldg((const float4*)(A  + (size_t)(m0+r1_)*K + kt+16 + kq1*4));
            bv0 = __ldg((const float4*)(Bw + (size_t)(n0+r0_)*K + kt+16 + kq0*4));
            bv1 = __ldg((const float4*)(Bw + (size_t)(n0+r1_)*K + kt+16 + kq1*4));
        }
#pragma unroll
        for(int k=0;k<16;k++){
            float4 a0 = *(const float4*)&As[k][ty*8];
            float4 a1 = *(const float4*)&As[k][ty*8+4];
            u64 b0 = *(const u64*)&Bs[k][tx*2];
            u64 b1 = *(const u64*)&Bs[k][tx*2 + 32];
            u64 b2 = *(const u64*)&Bs[k][tx*2 + 64];
            u64 b3 = *(const u64*)&Bs[k][tx*2 + 96];
            float af[8] = {a0.x,a0.y,a0.z,a0.w,a1.x,a1.y,a1.z,a1.w};
#pragma unroll
            for(int i=0;i<8;i++){
                u64 aa = pack2(af[i], af[i]);
                acc[i][0] = fma2(aa, b0, acc[i][0]);
                acc[i][1] = fma2(aa, b1, acc[i][1]);
                acc[i][2] = fma2(aa, b2, acc[i][2]);
                acc[i][3] = fma2(aa, b3, acc[i][3]);
            }
        }
        if(more){
            __syncthreads();
            As[kq0*4+0][r0_]=av0.x; As[kq0*4+1][r0_]=av0.y; As[kq0*4+2][r0_]=av0.z; As[kq0*4+3][r0_]=av0.w;
            As[kq1*4+0][r1_]=av1.x; As[kq1*4+1][r1_]=av1.y; As[kq1*4+2][r1_]=av1.z; As[kq1*4+3][r1_]=av1.w;
            Bs[kq0*4+0][r0_]=bv0.x; Bs[kq0*4+1][r0_]=bv0.y; Bs[kq0*4+2][r0_]=bv0.z; Bs[kq0*4+3][r0_]=bv0.w;
            Bs[kq1*4+0][r1_]=bv1.x; Bs[kq1*4+1][r1_]=bv1.y; Bs[kq1*4+2][r1_]=bv1.z; Bs[kq1*4+3][r1_]=bv1.w;
            __syncthreads();
        }
    }
#pragma unroll
    for(int i=0;i<8;i++){
        float* cp = C + (size_t)(m0 + ty*8 + i)*N + n0;
#pragma unroll
        for(int j=0;j<4;j++){
            float2 v = unp2(acc[i][j]);
            int col = 32*j + 2*tx;
            if(bias){
                v.x += __ldg(&bias[n0 + col    ]);
                v.y += __ldg(&bias[n0 + col + 1]);
            }
            *(float2*)(cp + col) = v;
        }
    }
}

// ---------------- merged levelizer (64 CTAs x 512, 2 internal grid barriers) ----------
__device__ __forceinline__ void gbar64(unsigned &ls){
    __syncthreads();
    if(threadIdx.x == 0){
        unsigned s = ls ^ 1u;
        __threadfence();
        unsigned a = atomicAdd(&g_cnt2, 1u);
        if(a == 63u){
            atomicExch(&g_cnt2, 0u);
            atomicExch(&g_sns, s);
        } else {
            while(atomicAdd(&g_sns, 0u) != s) __nanosleep(32);
        }
        __threadfence();
        ls = s;
    }
    __syncthreads();
}

__global__ __launch_bounds__(512)
void lvlall_kernel(const int* __restrict__ father)
{
    __shared__ int anc[2][512], dep[2][512], slvl[512], cnt[512];
    int t = threadIdx.x, b = blockIdx.x;
    unsigned ls = 0;

    int f  = __ldg(&father[b*T_ + t]);
    int fx = min(f, t-1) + 1;                  // in [0, t]
    anc[0][t] = fx - 1;
    dep[0][t] = (fx > 0) ? 1 : 0;
    cnt[t] = 0;
    __syncthreads();
#pragma unroll
    for(int r=0; r<9; r++){
        int cur = r & 1, nxt = cur ^ 1;
        int a = anc[cur][t], d = dep[cur][t];
        if(a >= 0){ d += dep[cur][a]; a = anc[cur][a]; }
        anc[nxt][t] = a; dep[nxt][t] = d;
        __syncthreads();
    }
    int L = dep[1][t];
    slvl[t] = L;
    atomicAdd(&cnt[L], 1);
    __syncthreads();
    int rk = 0;
    for(int tp=0; tp<t; tp++) rk += (slvl[tp] == L);
    g_cntB[b*512 + t] = cnt[t];

    gbar64(ls);

    if(b == 0){
        __shared__ int off[513];
        int s = 0;
        for(int bb=0; bb<B_; bb++) s += g_cntB[bb*512 + t];
        slvl[t] = s;
        __syncthreads();
        if(t == 0){
            int run = 0, D = 1;
            for(int i=0;i<512;i++){
                off[i] = run; run += slvl[i];
                if(slvl[i] > 0) D = i+1;
            }
            off[512] = run;
            g_D[0] = D;
            g_bar  = 0;
        }
        __syncthreads();
        g_lvlOff[t] = off[t];
        if(t == 0) g_lvlOff[512] = off[512];
        int run2 = off[t];
        for(int bb=0; bb<B_; bb++){
            g_off2[t*B_ + bb] = run2;
            run2 += g_cntB[bb*512 + t];
        }
    }

    gbar64(ls);

    int slot = g_off2[L*B_ + b] + rk;
    g_nodes[slot] = (b << 20) | (t << 10) | fx;
    int z = b*512 + t;
    if(z < BH_){ g_h[z] = 0.0f; g_c[z] = 0.0f; }
}

// ---------------- persistent levelized scan (R13 base + node-pair ILP) ----------------
// 288 CTAs = 18 M-slots x 16 unit-ranks. CTA(rank): units [16r,16r+16) -> 64 gate
// rows; thread: 2 rows x 32 K of W_hh (64 regs). cp.async double-buffered h gather,
// gx/c/mask prefetched to regs. Dots process NODE PAIRS (4 fma2 chains + batched shfl).
struct ScanSm {
    float hs[2][32*288];  // double-buffered gather: 32 nodes x (8 chunks x 36 floats)
    float qb[32*64];      // gates per node (lr = gate*16 + unit)
};

__global__ __launch_bounds__(256, 2)
void scan_kernel(const float* __restrict__ W_hh, const float* __restrict__ b_hh,
                 const float* __restrict__ mask, float* __restrict__ out)
{
    extern __shared__ __align__(16) char smraw[];
    ScanSm* S = (ScanSm*)smraw;
    u32 hs_s = (u32)__cvta_generic_to_shared(&S->hs[0][0]);

    int tid  = threadIdx.x;
    int rank = blockIdx.x & 15;
    int msl  = blockIdx.x >> 4;
    int u0   = rank * 16;
    int kidx = tid & 7;
    int rg   = tid >> 3;                       // 0..31
    int cu   = tid & 15;                       // cell unit
    int gu   = u0 + cu;
    int cn0  = tid >> 4;                       // cell node base 0..15

    // W_hh slice: 2 gate rows x 32 K-floats (16 u64 each) -> 64 regs
    u64 w2[32];
#pragma unroll
    for(int rj=0; rj<2; rj++){
        int lr   = rg*2 + rj;                  // 0..63
        int grow = (lr>>4)*256 + u0 + (lr&15);
        const u64* Wp = (const u64*)(W_hh + (size_t)grow*256 + kidx*32);
#pragma unroll
        for(int i=0;i<16;i++) w2[rj*16+i] = __ldg(&Wp[i]);
    }
    float bh4[4];
#pragma unroll
    for(int g=0; g<4; g++) bh4[g] = __ldg(&b_hh[g*256 + gu]);

    int D = g_D[0];
    unsigned phase = 0;

    for(int l=0; l<D; l++){
        int o0 = g_lvlOff[l], o1 = g_lvlOff[l+1];
        int ntile = (o1 - o0 + 31) >> 5;

        // prologue: async-stage first tile into buf 0
        int buf = 0;
        if(msl < ntile){
            int base = o0 + msl*32;
            int nn   = min(32, o1 - base);
#pragma unroll
            for(int j=0;j<8;j++){
                int lin = j*256 + tid;
                int n = lin >> 6, p = lin & 63;
                if(n < nn){
                    int v  = __ldg(&g_nodes[base + n]);
                    int fx = v & 1023, bb = v >> 20;
                    const float4* src = (const float4*)(g_h + (size_t)fx*BH_ + bb*256) + p;
                    cpasync16(hs_s + (u32)((n*288 + (p>>3)*36 + (p&7)*4)*4), src);
                }
            }
        }
        CP_COMMIT();

        for(int mt = msl; mt < ntile; mt += MPAR_){
            int base = o0 + mt*32;
            int nn   = min(32, o1 - base);

            // prefetch cell operands into regs (independent of dots)
            float gxp[2][4], cpp[2], mvp[2];
            int   tt[2], tb[2];
#pragma unroll
            for(int e=0;e<2;e++){
                int n = e*16 + cn0;
                if(n < nn){
                    int v  = __ldg(&g_nodes[base + n]);
                    int fx = v & 1023; tt[e] = (v >> 10) & 1023; tb[e] = v >> 20;
                    size_t gxr = ((size_t)tt[e]*B_ + tb[e])*G_;
#pragma unroll
                    for(int g=0; g<4; g++) gxp[e][g] = __ldg(&g_gx[gxr + g*256 + gu]);
                    cpp[e] = __ldg(&g_c[(size_t)fx*BH_ + tb[e]*256 + gu]);
                    mvp[e] = __ldg(&mask[tb[e]*T_ + tt[e]]);
                }
            }

            CP_WAIT0();
            __syncthreads();          // staged tile visible to all

            // async-stage next tile into the other buffer (overlaps dots)
            int mtn = mt + MPAR_;
            if(mtn < ntile){
                int basen = o0 + mtn*32;
                int nnn   = min(32, o1 - basen);
                u32 dstb  = hs_s + (u32)((buf^1)*32*288*4);
#pragma unroll
                for(int j=0;j<8;j++){
                    int lin = j*256 + tid;
                    int n = lin >> 6, p = lin & 63;
                    if(n < nnn){
                        int v  = __ldg(&g_nodes[basen + n]);
                        int fx = v & 1023, bb = v >> 20;
                        const float4* src = (const float4*)(g_h + (size_t)fx*BH_ + bb*256) + p;
                        cpasync16(dstb + (u32)((n*288 + (p>>3)*36 + (p&7)*4)*4), src);
                    }
                }
            }
            CP_COMMIT();

            // dots from hs[buf]: NODE PAIRS -> 4 independent fma2 chains
            const float* hsb = &S->hs[buf][0];
            for(int n=0; n<nn; n+=2){
                bool has1 = (n+1 < nn);
                const u64* hq0 = (const u64*)(hsb +  n   *288 + kidx*36);
                const u64* hq1 = (const u64*)(hsb + (n+1)*288 + kidx*36);
                u64 a0=0ull, a1=0ull, b0=0ull, b1=0ull;
#pragma unroll
                for(int i=0;i<16;i++){
                    u64 h0 = hq0[i];
                    u64 h1 = hq1[i];            // stale-safe beyond nn (buffer allocated)
                    a0 = fma2(w2[   i], h0, a0);
                    a1 = fma2(w2[16+i], h0, a1);
                    b0 = fma2(w2[   i], h1, b0);
                    b1 = fma2(w2[16+i], h1, b1);
                }
                float2 ra0=unp2(a0), ra1=unp2(a1), rb0=unp2(b0), rb1=unp2(b1);
                float q00=ra0.x+ra0.y, q01=ra1.x+ra1.y;
                float q10=rb0.x+rb0.y, q11=rb1.x+rb1.y;
#pragma unroll
                for(int m=1;m<8;m<<=1){
                    q00 += __shfl_xor_sync(0xffffffffu, q00, m);
                    q01 += __shfl_xor_sync(0xffffffffu, q01, m);
                    q10 += __shfl_xor_sync(0xffffffffu, q10, m);
                    q11 += __shfl_xor_sync(0xffffffffu, q11, m);
                }
                if(kidx == 0){
                    S->qb[n*64 + rg*2 + 0] = q00;
                    S->qb[n*64 + rg*2 + 1] = q01;
                    if(has1){
                        S->qb[(n+1)*64 + rg*2 + 0] = q10;
                        S->qb[(n+1)*64 + rg*2 + 1] = q11;
                    }
                }
            }
            __syncthreads();

            // fused LSTM cell: 32 nodes x 16 units -> 2 per thread
#pragma unroll
            for(int e=0;e<2;e++){
                int n = e*16 + cn0;
                if(n < nn){
                    float gi = S->qb[n*64 +      cu] + gxp[e][0] + bh4[0];
                    float gf = S->qb[n*64 + 16 + cu] + gxp[e][1] + bh4[1];
                    float gg = S->qb[n*64 + 32 + cu] + gxp[e][2] + bh4[2];
                    float go = S->qb[n*64 + 48 + cu] + gxp[e][3] + bh4[3];
                    float cv = sigm(gf)*cpp[e] + sigm(gi)*tanh_f(gg);
                    float hv = sigm(go)*tanh_f(cv);
                    size_t o = (size_t)(tt[e]+1)*BH_ + tb[e]*256 + gu;
                    g_h[o] = hv;
                    g_c[o] = cv;
                    out[(size_t)tb[e]*(T_*H_) + (size_t)tt[e]*H_ + gu] = hv*mvp[e];
                }
            }
            buf ^= 1;
        }

        // grid barrier between levels (monotonic; g_bar reset by lvlall each call)
        phase++;
        __threadfence();
        __syncthreads();
        if(tid == 0){
            atomicAdd(&g_bar, 1u);
            unsigned target = phase * NCTA_;
            while(*((volatile unsigned*)&g_bar) < target) __nanosleep(64);
            __threadfence();
        }
        __syncthreads();
    }
}

// ---------------- masked max epilogue ----------------
__global__ __launch_bounds__(256)
void maxes_kernel(const float* __restrict__ mask, float* __restrict__ out)
{
    int idx = blockIdx.x*256 + threadIdx.x;     // 0..BH-1
    int b = idx >> 8, u = idx & 255;
    float hm = -1e30f, cm = -1e30f;
    for(int t=0; t<T_; t++){
        float h  = out[(size_t)b*(T_*H_) + (size_t)t*H_ + u];
        float mv = __ldg(&mask[b*T_ + t]);
        float c  = g_c[(size_t)(t+1)*BH_ + b*256 + u] * mv;
        hm = fmaxf(hm, h);
        cm = fmaxf(cm, c);
    }
    size_t base = (size_t)2*B_*T_*H_;
    out[base +        idx] = hm;
    out[base + BH_ +  idx] = cm;
}

extern "C" void kernel_launch(void* const* d_in, const int* in_sizes, int n_in,
                              void* d_out, int out_size)
{
    const int*   node   = (const int*)  d_in[0];
    const int*   rel    = (const int*)  d_in[1];
    const int*   father = (const int*)  d_in[2];
    const float* mask   = (const float*)d_in[3];
    const float* emb    = (const float*)d_in[4];
    const float* W_ih   = (const float*)d_in[5];
    const float* W_hh   = (const float*)d_in[6];
    const float* b_ih   = (const float*)d_in[7];
    const float* b_hh   = (const float*)d_in[8];
    const float* W_h    = (const float*)d_in[9];
    float* out = (float*)d_out;

    float *px, *pgx;
    cudaGetSymbolAddress((void**)&px,  g_x);
    cudaGetSymbolAddress((void**)&pgx, g_gx);

    embed_kernel<<<(B_*T_)/4, 128>>>(node, rel, emb);           // launch 1

    dim3 g1(G_/128, (B_*T_)/128);
    sgemm_nt<<<g1, 256>>>(px, W_ih, b_ih, pgx, B_*T_, G_, 256); // launch 2

    lvlall_kernel<<<B_, 512>>>(father);                          // launch 3

    cudaFuncSetAttribute(scan_kernel, cudaFuncAttributeMaxDynamicSharedMemorySize,
                         (int)sizeof(ScanSm));
    scan_kernel<<<NCTA_, 256, sizeof(ScanSm)>>>(W_hh, b_hh, mask, out);  // launch 4 (profiled)

    maxes_kernel<<<BH_/256, 256>>>(mask, out);                   // launch 5

    dim3 g2(H_/128, (B_*T_)/128);
    sgemm_nt<<<g2, 256>>>(out, W_h, (const float*)nullptr,
                          out + (size_t)B_*T_*H_, B_*T_, H_, 256);  // launch 6
}